// round 1
// baseline (speedup 1.0000x reference)
#include <cuda_runtime.h>
#include <cstdint>

// MTLSTM: B=128, T=512, K=12, H=256, OUT=1
// Persistent kernel: 128 CTAs x 256 threads, tf32 mma.sync, software grid barrier.

#define NB 128
#define NT 512
#define NKF 12
#define NH 256
#define GRID 128
#define THREADS 256

// Persistent state (double buffered) + grid barrier counter.
__device__ float g_h[2][NB * NH];
__device__ float g_c[2][NB * NH];
__device__ unsigned g_bar;

__device__ __forceinline__ uint32_t f2tf32(float x) {
    uint32_t r;
    asm("cvt.rna.tf32.f32 %0, %1;" : "=r"(r) : "f"(x));
    return r;
}

__device__ __forceinline__ void mma_tf32(float acc[4],
                                         uint32_t a0, uint32_t a1, uint32_t a2, uint32_t a3,
                                         uint32_t b0, uint32_t b1) {
    asm volatile(
        "mma.sync.aligned.m16n8k8.row.col.f32.tf32.tf32.f32 "
        "{%0,%1,%2,%3}, {%4,%5,%6,%7}, {%8,%9}, {%0,%1,%2,%3};\n"
        : "+f"(acc[0]), "+f"(acc[1]), "+f"(acc[2]), "+f"(acc[3])
        : "r"(a0), "r"(a1), "r"(a2), "r"(a3), "r"(b0), "r"(b1));
}

__device__ __forceinline__ float sig_f(float x) {
    return 1.0f / (1.0f + __expf(-x));
}
__device__ __forceinline__ float tanh_f(float x) {
    x = fminf(15.0f, fmaxf(-15.0f, x));
    float e = __expf(2.0f * x);
    return (e - 1.0f) / (e + 1.0f);
}

// Shared memory layout (floats):
//  [0, 16384)            : B fragments, 8 ntiles x 32 ksteps x 32 lanes, float2 each
//  [16384, 16384+4224)   : Csm[64][66]
//  [20608, 20608+192)    : sWih[16][12]
//  [20800, 20800+16)     : sBias[16]
//  [20816, 20816+48)     : sBde[12][4]
#define SMEM_FLOATS (16384 + 64 * 66 + 192 + 16 + 48)

__global__ void __launch_bounds__(THREADS, 1)
mtlstm_persistent(const float* __restrict__ xd, const float* __restrict__ dtp,
                  const float* __restrict__ Wih, const float* __restrict__ Whh,
                  const float* __restrict__ bias, const float* __restrict__ Wd,
                  const float* __restrict__ bde) {
    extern __shared__ float sm[];
    float2* Bf = reinterpret_cast<float2*>(sm);      // 8192 float2
    float* Csm = sm + 16384;                          // 64*66
    float* sWih = sm + 16384 + 64 * 66;               // 16*12
    float* sBias = sWih + 192;                        // 16
    float* sBde = sBias + 16;                         // 48

    const int tid = threadIdx.x;
    const int mh = blockIdx.x & 1;        // m-half: batch rows [mh*64, mh*64+64)
    const int ns = blockIdx.x >> 1;       // o-slice
    const int o0 = ns * 4;                // 4 hidden channels per CTA

    // ---- Fill tf32 B fragments in SMEM (step-invariant) ----
    // CTA column index ncol in [0,64):
    //   ncol < 16 : gate columns, ncol = g*4 + ol  (g: i,f,g,o), uses A = h
    //   ncol >= 16: decomp columns, ncol = 16 + kf*4 + ol,       uses A = c
    for (int pi = tid >> 5; pi < 256; pi += 8) {   // pi = ntile*32 + kk
        int ntile = pi >> 5;
        int kk = pi & 31;
        int lane = tid & 31;
        int krow = kk * 8 + (lane & 3);
        int ncol = ntile * 8 + (lane >> 2);
        float b0, b1;
        if (ncol < 16) {
            int g = ncol >> 2, ol = ncol & 3;
            const float* r = Whh + (size_t)(g * 256 + o0 + ol) * 256;
            b0 = r[krow];
            b1 = r[krow + 4];
        } else {
            int idx = ncol - 16;
            int kf = idx >> 2, ol = idx & 3;
            const float* r = Wd + (size_t)(kf * 256 + o0 + ol) * 256;
            b0 = r[krow];
            b1 = r[krow + 4];
        }
        uint32_t u0 = f2tf32(b0), u1 = f2tf32(b1);
        Bf[pi * 32 + lane] = make_float2(__uint_as_float(u0), __uint_as_float(u1));
    }
    if (tid < 16) {
        int g = tid >> 2, ol = tid & 3;
        sBias[tid] = bias[g * 256 + o0 + ol];
        for (int k = 0; k < NKF; ++k)
            sWih[tid * NKF + k] = Wih[(g * 256 + o0 + ol) * NKF + k];
    }
    if (tid < 48) {
        int kf = tid >> 2, ol = tid & 3;
        sBde[tid] = bde[kf * 256 + o0 + ol];
    }
    __syncthreads();

    // ---- warp / lane mapping for MMA ----
    const int w = tid >> 5;
    const int lane = tid & 31;
    const int gq = lane >> 2;     // 0..7
    const int tq = lane & 3;      // 0..3
    const int mtile = w >> 1;     // 0..3  (16 rows each, within this CTA's 64)
    const int ng = w & 1;         // n-group: 0 -> ntiles 0..3, 1 -> ntiles 4..7

    const int arow0 = mh * 64 + mtile * 16 + gq;   // global batch row for a0/a2
    // a1/a3 row = arow0 + 8

    // ---- epilogue mapping: thread -> (local b, local o) ----
    const int eb = tid >> 2;            // 0..63
    const int eol = tid & 3;            // 0..3
    const int gb = mh * 64 + eb;        // global batch row
    const int go = o0 + eol;            // global hidden channel

    const float* xrow_base = xd + ((size_t)gb * NT) * NKF;
    const float* drow_base = dtp + ((size_t)gb * NT) * NKF;

    unsigned bar_target = 0;

    for (int t = 0; t < NT; ++t) {
        const int p = t & 1;
        const float* hb = g_h[p];
        const float* cb = g_c[p];

        float acc[4][4];
#pragma unroll
        for (int i = 0; i < 4; ++i)
#pragma unroll
            for (int j = 0; j < 4; ++j) acc[i][j] = 0.0f;

        const float* hp = hb + (size_t)arow0 * 256 + tq;
        const float* cp = cb + (size_t)arow0 * 256 + tq;

#pragma unroll 4
        for (int kk = 0; kk < 32; ++kk) {
            const int k0 = kk * 8;
            uint32_t ah0 = 0, ah1 = 0, ah2 = 0, ah3 = 0;
            if (ng == 0) {
                ah0 = f2tf32(hp[k0]);
                ah1 = f2tf32(hp[8 * 256 + k0]);
                ah2 = f2tf32(hp[k0 + 4]);
                ah3 = f2tf32(hp[8 * 256 + k0 + 4]);
            }
            uint32_t ac0 = f2tf32(cp[k0]);
            uint32_t ac1 = f2tf32(cp[8 * 256 + k0]);
            uint32_t ac2 = f2tf32(cp[k0 + 4]);
            uint32_t ac3 = f2tf32(cp[8 * 256 + k0 + 4]);

#pragma unroll
            for (int nt = 0; nt < 4; ++nt) {
                const int ntile = ng * 4 + nt;
                float2 b = Bf[(ntile * 32 + kk) * 32 + lane];
                uint32_t b0 = __float_as_uint(b.x);
                uint32_t b1 = __float_as_uint(b.y);
                if (ntile < 2)
                    mma_tf32(acc[nt], ah0, ah1, ah2, ah3, b0, b1);
                else
                    mma_tf32(acc[nt], ac0, ac1, ac2, ac3, b0, b1);
            }
        }

        // ---- dump accumulators to SMEM ----
#pragma unroll
        for (int nt = 0; nt < 4; ++nt) {
            const int col0 = (ng * 4 + nt) * 8 + 2 * tq;
            const int r0 = mtile * 16 + gq;
            *reinterpret_cast<float2*>(&Csm[r0 * 66 + col0]) =
                make_float2(acc[nt][0], acc[nt][1]);
            *reinterpret_cast<float2*>(&Csm[(r0 + 8) * 66 + col0]) =
                make_float2(acc[nt][2], acc[nt][3]);
        }
        __syncthreads();

        // ---- epilogue: gates + decomp + state update ----
        {
            const float* xrow = xrow_base + (size_t)t * NKF;
            const float* drow = drow_base + (size_t)t * NKF;
            float x[12];
            {
                float4 x0 = reinterpret_cast<const float4*>(xrow)[0];
                float4 x1 = reinterpret_cast<const float4*>(xrow)[1];
                float4 x2 = reinterpret_cast<const float4*>(xrow)[2];
                x[0] = x0.x; x[1] = x0.y; x[2] = x0.z; x[3] = x0.w;
                x[4] = x1.x; x[5] = x1.y; x[6] = x1.z; x[7] = x1.w;
                x[8] = x2.x; x[9] = x2.y; x[10] = x2.z; x[11] = x2.w;
            }
            float d[12];
            {
                float4 d0 = reinterpret_cast<const float4*>(drow)[0];
                float4 d1 = reinterpret_cast<const float4*>(drow)[1];
                float4 d2 = reinterpret_cast<const float4*>(drow)[2];
                d[0] = d0.x; d[1] = d0.y; d[2] = d0.z; d[3] = d0.w;
                d[4] = d1.x; d[5] = d1.y; d[6] = d1.z; d[7] = d1.w;
                d[8] = d2.x; d[9] = d2.y; d[10] = d2.z; d[11] = d2.w;
            }

            float pre[4];
#pragma unroll
            for (int g = 0; g < 4; ++g) {
                float s = Csm[eb * 66 + g * 4 + eol] + sBias[g * 4 + eol];
                const float* wr = &sWih[(g * 4 + eol) * NKF];
#pragma unroll
                for (int k = 0; k < NKF; ++k) s += x[k] * wr[k];
                pre[g] = s;
            }
            float ig = sig_f(pre[0]);
            float fg = sig_f(pre[1]);
            float gg = tanh_f(pre[2]);
            float og = sig_f(pre[3]);

            float S = 0.0f;
#pragma unroll
            for (int k = 0; k < NKF; ++k) {
                float cs = tanh_f(Csm[eb * 66 + 16 + k * 4 + eol] + sBde[k * 4 + eol]);
                float decay = 1.0f / __logf(2.71828182845904523536f + d[k]);
                S += cs * (decay - 1.0f);
            }

            float cprev = cb[gb * 256 + go];
            float cn = fg * (cprev + S) + ig * gg;
            float hn = og * tanh_f(cn);
            g_c[1 - p][gb * 256 + go] = cn;
            g_h[1 - p][gb * 256 + go] = hn;
        }

        // ---- software grid barrier ----
        bar_target += GRID;
        __threadfence();
        __syncthreads();
        if (tid == 0) {
            atomicAdd(&g_bar, 1u);
            while (*(volatile unsigned*)&g_bar < bar_target) { }
            __threadfence();
        }
        __syncthreads();
    }
}

__global__ void mtlstm_init() {
    int i = blockIdx.x * blockDim.x + threadIdx.x;
    if (i == 0) g_bar = 0u;
    for (; i < NB * NH; i += gridDim.x * blockDim.x) {
        g_h[0][i] = 0.0f;
        g_c[0][i] = 0.0f;
        g_h[1][i] = 0.0f;
        g_c[1][i] = 0.0f;
    }
}

__global__ void mtlstm_out(const float* __restrict__ lw, const float* __restrict__ lb,
                           float* __restrict__ out) {
    const int b = blockIdx.x;
    const int lane = threadIdx.x;
    const float* h = g_h[0] + b * 256;   // step 511 writes buffer 0
    float s = 0.0f;
    for (int dd = lane; dd < 256; dd += 32) s += h[dd] * lw[dd];
#pragma unroll
    for (int off = 16; off; off >>= 1) s += __shfl_xor_sync(0xffffffffu, s, off);
    if (lane == 0) out[b] = s + lb[0];
}

extern "C" void kernel_launch(void* const* d_in, const int* in_sizes, int n_in,
                              void* d_out, int out_size) {
    const float* xd  = (const float*)d_in[0];
    const float* dtp = (const float*)d_in[1];
    const float* wih = (const float*)d_in[2];
    const float* whh = (const float*)d_in[3];
    const float* bia = (const float*)d_in[4];
    const float* wd  = (const float*)d_in[5];
    const float* bde = (const float*)d_in[6];
    const float* lw  = (const float*)d_in[7];
    const float* lb  = (const float*)d_in[8];
    float* out = (float*)d_out;

    const size_t smem_bytes = SMEM_FLOATS * sizeof(float);   // ~83.5 KB
    cudaFuncSetAttribute(mtlstm_persistent,
                         cudaFuncAttributeMaxDynamicSharedMemorySize,
                         (int)smem_bytes);

    mtlstm_init<<<64, 256>>>();
    mtlstm_persistent<<<GRID, THREADS, smem_bytes>>>(xd, dtp, wih, whh, bia, wd, bde);
    mtlstm_out<<<NB, 32>>>(lw, lb, out);
}

// round 2
// speedup vs baseline: 3.0129x; 3.0129x over previous
#include <cuda_runtime.h>
#include <cstdint>

// MTLSTM: B=128, T=512, K=12, H=256, OUT=1
// Persistent kernel: 128 CTAs x 256 threads, tf32 mma.sync with B (weights) in
// registers, A (states) staged via cp.async.cg, software grid barrier.

#define NB 128
#define NT 512
#define NKF 12
#define NH 256
#define GRID 128
#define THREADS 256

// Persistent state (double buffered, tf32-rounded fp32 bits) + barrier + decay scratch.
__device__ float g_h[2][NB * NH];
__device__ float g_c[2][NB * NH];
__device__ float g_dec[NB * NT * NKF];   // (1/ln(e+dt) - 1), precomputed
__device__ unsigned g_bar;

__device__ __forceinline__ uint32_t f2tf32(float x) {
    uint32_t r;
    asm("cvt.rna.tf32.f32 %0, %1;" : "=r"(r) : "f"(x));
    return r;
}

__device__ __forceinline__ void mma_tf32(float acc[4],
                                         uint32_t a0, uint32_t a1, uint32_t a2, uint32_t a3,
                                         uint32_t b0, uint32_t b1) {
    asm volatile(
        "mma.sync.aligned.m16n8k8.row.col.f32.tf32.tf32.f32 "
        "{%0,%1,%2,%3}, {%4,%5,%6,%7}, {%8,%9}, {%0,%1,%2,%3};\n"
        : "+f"(acc[0]), "+f"(acc[1]), "+f"(acc[2]), "+f"(acc[3])
        : "r"(a0), "r"(a1), "r"(a2), "r"(a3), "r"(b0), "r"(b1));
}

__device__ __forceinline__ void cp16(void* dst, const void* src) {
    uint32_t d = (uint32_t)__cvta_generic_to_shared(dst);
    asm volatile("cp.async.cg.shared.global [%0], [%1], 16;\n" :: "r"(d), "l"(src));
}
__device__ __forceinline__ void cp_commit() {
    asm volatile("cp.async.commit_group;\n" ::: "memory");
}
__device__ __forceinline__ void cp_wait(int g4) {
    // g4 is a compile-time constant after unrolling; branches fold.
    if (g4 == 0)      asm volatile("cp.async.wait_group 3;\n" ::: "memory");
    else if (g4 == 1) asm volatile("cp.async.wait_group 2;\n" ::: "memory");
    else if (g4 == 2) asm volatile("cp.async.wait_group 1;\n" ::: "memory");
    else              asm volatile("cp.async.wait_group 0;\n" ::: "memory");
}

__device__ __forceinline__ float sig_f(float x) {
    return 1.0f / (1.0f + __expf(-x));
}
__device__ __forceinline__ float tanh_f(float x) {
    x = fminf(15.0f, fmaxf(-15.0f, x));
    float e = __expf(2.0f * x);
    return (e - 1.0f) / (e + 1.0f);
}

// Shared memory layout (floats):
//  hA  : 64 rows x 260 (padded)  = 16640
//  cA  : 64 rows x 260           = 16640
//  Csm : 64 x 66                 = 4224
//  sWih: 16 x 12 = 192, sBias: 16, sBde: 48
#define SMEM_FLOATS (16640 * 2 + 64 * 66 + 192 + 16 + 48)

__global__ void __launch_bounds__(THREADS, 1)
mtlstm_persistent(const float* __restrict__ xd, const float* __restrict__ dtp,
                  const float* __restrict__ Wih, const float* __restrict__ Whh,
                  const float* __restrict__ bias, const float* __restrict__ Wd,
                  const float* __restrict__ bde, const float* __restrict__ lw,
                  const float* __restrict__ lb, float* __restrict__ out) {
    extern __shared__ float sm[];
    float* hA = sm;                        // 64*260
    float* cA = sm + 16640;                // 64*260
    float* Csm = sm + 2 * 16640;           // 64*66
    float* sWih = Csm + 64 * 66;           // 16*12
    float* sBias = sWih + 192;             // 16
    float* sBde = sBias + 16;              // 48

    const int tid = threadIdx.x;
    const int mh = blockIdx.x & 1;         // batch half: rows [mh*64, mh*64+64)
    const int ns = blockIdx.x >> 1;        // o-slice
    const int o0 = ns * 4;                 // 4 hidden channels per CTA

    // ---- small tables ----
    if (tid < 16) {
        int g = tid >> 2, ol = tid & 3;
        sBias[tid] = bias[g * 256 + o0 + ol];
        for (int k = 0; k < NKF; ++k)
            sWih[tid * NKF + k] = Wih[(g * 256 + o0 + ol) * NKF + k];
    }
    if (tid < 48) {
        int kf = tid >> 2, ol = tid & 3;
        sBde[tid] = bde[kf * 256 + o0 + ol];
    }

    // ---- precompute decay-1 into global scratch (once, cooperatively) ----
    {
        const int gt = blockIdx.x * THREADS + tid;
        const int total = NB * NT * NKF;
        for (int i = gt; i < total; i += GRID * THREADS) {
            float v = dtp[i];
            g_dec[i] = 1.0f / __logf(2.71828182845904523536f + v) - 1.0f;
        }
    }

    // ---- warp / lane mapping ----
    const int w = tid >> 5;
    const int lane = tid & 31;
    const int gq = lane >> 2;      // 0..7
    const int tq = lane & 3;       // 0..3
    const int mpos = w >> 2;       // 0..1 : local rows [mpos*32, mpos*32+32)
    const int npos = w & 3;        // 0..3 : ntiles {2*npos, 2*npos+1}
    // npos==0 -> gate columns (A=h); npos 1..3 -> decomp columns (A=c)

    // ---- load B (weights) fragments into registers, tf32, once ----
    uint32_t breg[128];    // [nt(2)][kk(32)][2]
#pragma unroll
    for (int nt = 0; nt < 2; ++nt) {
        const int ntile = npos * 2 + nt;
        const int ncol = ntile * 8 + gq;
        const float* row;
        if (ncol < 16) {
            int g = ncol >> 2, ol = ncol & 3;
            row = Whh + (size_t)(g * 256 + o0 + ol) * 256;
        } else {
            int idx = ncol - 16;
            int kf = idx >> 2, ol = idx & 3;
            row = Wd + (size_t)(kf * 256 + o0 + ol) * 256;
        }
#pragma unroll
        for (int kk = 0; kk < 32; ++kk) {
            const int krow = kk * 8 + tq;
            breg[(nt * 32 + kk) * 2]     = f2tf32(row[krow]);
            breg[(nt * 32 + kk) * 2 + 1] = f2tf32(row[krow + 4]);
        }
    }

    const float* aBase = (npos == 0) ? hA : cA;
    const int r0 = mpos * 32 + gq;

    // ---- epilogue mapping: thread -> (local b, local o) ----
    const int eb = tid >> 2;
    const int eol = tid & 3;
    const int gb = mh * 64 + eb;
    const int go = o0 + eol;
    const float* xrow_base = xd + (size_t)gb * NT * NKF;
    const float* dec_base = g_dec + (size_t)gb * NT * NKF;
    float c_reg = 0.0f;

    __syncthreads();

    unsigned bar_target = 0;

    // pre-barrier: g_dec visible everywhere before first epilogue
    {
        bar_target += GRID;
        __threadfence();
        __syncthreads();
        if (tid == 0) {
            atomicAdd(&g_bar, 1u);
            while (*(volatile unsigned*)&g_bar < bar_target) { }
            __threadfence();
        }
        __syncthreads();
    }

    for (int t = 0; t < NT; ++t) {
        const int p = t & 1;   // read buffer p, write buffer 1-p

        // ---- stage states (t>0) : cp.async in 4 k-groups of 64 cols ----
        if (t > 0) {
            const float* hs = g_h[p] + (size_t)mh * 64 * 256;
            const float* cs = g_c[p] + (size_t)mh * 64 * 256;
#pragma unroll
            for (int g4 = 0; g4 < 4; ++g4) {
#pragma unroll
                for (int j = 0; j < 8; ++j) {
                    const int cid = j * 256 + tid;       // 0..2047
                    const int mat = cid >> 10;           // 0=h, 1=c
                    const int row = (cid >> 4) & 63;
                    const int ch = cid & 15;
                    const int col = g4 * 64 + ch * 4;
                    const float* src = (mat ? cs : hs) + row * 256 + col;
                    float* dst = (mat ? cA : hA) + row * 260 + col;
                    cp16(dst, src);
                }
                cp_commit();
            }
        }

        float acc[2][2][4];
#pragma unroll
        for (int a = 0; a < 2; ++a)
#pragma unroll
            for (int b = 0; b < 2; ++b)
#pragma unroll
                for (int c = 0; c < 4; ++c) acc[a][b][c] = 0.0f;

        if (t > 0) {
#pragma unroll
            for (int g4 = 0; g4 < 4; ++g4) {
                cp_wait(g4);
                __syncthreads();
#pragma unroll
                for (int kk8 = 0; kk8 < 8; ++kk8) {
                    const int kk = g4 * 8 + kk8;
                    const int k0 = kk * 8;
                    uint32_t a[2][4];
#pragma unroll
                    for (int mt = 0; mt < 2; ++mt) {
                        const float* ar = aBase + (size_t)(r0 + mt * 16) * 260 + k0 + tq;
                        a[mt][0] = __float_as_uint(ar[0]);
                        a[mt][1] = __float_as_uint(ar[8 * 260]);
                        a[mt][2] = __float_as_uint(ar[4]);
                        a[mt][3] = __float_as_uint(ar[8 * 260 + 4]);
                    }
#pragma unroll
                    for (int mt = 0; mt < 2; ++mt)
#pragma unroll
                        for (int nt = 0; nt < 2; ++nt)
                            mma_tf32(acc[mt][nt],
                                     a[mt][0], a[mt][1], a[mt][2], a[mt][3],
                                     breg[(nt * 32 + kk) * 2],
                                     breg[(nt * 32 + kk) * 2 + 1]);
                }
            }
        }

        // ---- dump accumulators to Csm ----
#pragma unroll
        for (int mt = 0; mt < 2; ++mt)
#pragma unroll
            for (int nt = 0; nt < 2; ++nt) {
                const int ntile = npos * 2 + nt;
                const int col0 = ntile * 8 + 2 * tq;
                const int rr = mpos * 32 + mt * 16 + gq;
                *reinterpret_cast<float2*>(&Csm[rr * 66 + col0]) =
                    make_float2(acc[mt][nt][0], acc[mt][nt][1]);
                *reinterpret_cast<float2*>(&Csm[(rr + 8) * 66 + col0]) =
                    make_float2(acc[mt][nt][2], acc[mt][nt][3]);
            }
        __syncthreads();

        // ---- epilogue: gates + decomp + state update (one thread per (b,o)) ----
        {
            const float* xrow = xrow_base + (size_t)t * NKF;
            const float* drow = dec_base + (size_t)t * NKF;
            float x[12], d[12];
            {
                float4 x0 = reinterpret_cast<const float4*>(xrow)[0];
                float4 x1 = reinterpret_cast<const float4*>(xrow)[1];
                float4 x2 = reinterpret_cast<const float4*>(xrow)[2];
                x[0] = x0.x; x[1] = x0.y; x[2] = x0.z; x[3] = x0.w;
                x[4] = x1.x; x[5] = x1.y; x[6] = x1.z; x[7] = x1.w;
                x[8] = x2.x; x[9] = x2.y; x[10] = x2.z; x[11] = x2.w;
                float4 d0 = reinterpret_cast<const float4*>(drow)[0];
                float4 d1 = reinterpret_cast<const float4*>(drow)[1];
                float4 d2 = reinterpret_cast<const float4*>(drow)[2];
                d[0] = d0.x; d[1] = d0.y; d[2] = d0.z; d[3] = d0.w;
                d[4] = d1.x; d[5] = d1.y; d[6] = d1.z; d[7] = d1.w;
                d[8] = d2.x; d[9] = d2.y; d[10] = d2.z; d[11] = d2.w;
            }

            float pre[4];
#pragma unroll
            for (int g = 0; g < 4; ++g) {
                float s = Csm[eb * 66 + g * 4 + eol] + sBias[g * 4 + eol];
                const float* wr = &sWih[(g * 4 + eol) * NKF];
#pragma unroll
                for (int k = 0; k < NKF; ++k) s += x[k] * wr[k];
                pre[g] = s;
            }
            float ig = sig_f(pre[0]);
            float fg = sig_f(pre[1]);
            float gg = tanh_f(pre[2]);
            float og = sig_f(pre[3]);

            float S = 0.0f;
#pragma unroll
            for (int k = 0; k < NKF; ++k) {
                float cs = tanh_f(Csm[eb * 66 + 16 + k * 4 + eol] + sBde[k * 4 + eol]);
                S += cs * d[k];
            }

            float cn = fg * (c_reg + S) + ig * gg;
            c_reg = cn;
            float hn = og * tanh_f(cn);
            g_c[1 - p][gb * 256 + go] = __uint_as_float(f2tf32(cn));
            g_h[1 - p][gb * 256 + go] = __uint_as_float(f2tf32(hn));
        }

        // ---- software grid barrier ----
        bar_target += GRID;
        __threadfence();
        __syncthreads();
        if (tid == 0) {
            atomicAdd(&g_bar, 1u);
            while (*(volatile unsigned*)&g_bar < bar_target) { }
            __threadfence();
        }
        __syncthreads();
    }

    // ---- final output: CTA b computes out[b] (warp 0) ----
    if (w == 0) {
        const int b = blockIdx.x;
        const float* h = g_h[0] + b * 256;   // step 511 wrote buffer 0
        float s = 0.0f;
        for (int dd = lane; dd < 256; dd += 32) s += __ldcg(&h[dd]) * lw[dd];
#pragma unroll
        for (int off = 16; off; off >>= 1) s += __shfl_xor_sync(0xffffffffu, s, off);
        if (lane == 0) out[b] = s + lb[0];
    }
}

__global__ void mtlstm_barzero() {
    g_bar = 0u;
}

extern "C" void kernel_launch(void* const* d_in, const int* in_sizes, int n_in,
                              void* d_out, int out_size) {
    const float* xd  = (const float*)d_in[0];
    const float* dtp = (const float*)d_in[1];
    const float* wih = (const float*)d_in[2];
    const float* whh = (const float*)d_in[3];
    const float* bia = (const float*)d_in[4];
    const float* wd  = (const float*)d_in[5];
    const float* bde = (const float*)d_in[6];
    const float* lw  = (const float*)d_in[7];
    const float* lb  = (const float*)d_in[8];
    float* out = (float*)d_out;

    const size_t smem_bytes = SMEM_FLOATS * sizeof(float);   // ~151 KB
    cudaFuncSetAttribute(mtlstm_persistent,
                         cudaFuncAttributeMaxDynamicSharedMemorySize,
                         (int)smem_bytes);

    mtlstm_barzero<<<1, 1>>>();
    mtlstm_persistent<<<GRID, THREADS, smem_bytes>>>(xd, dtp, wih, whh, bia, wd,
                                                     bde, lw, lb, out);
}

// round 3
// speedup vs baseline: 5.3034x; 1.7602x over previous
#include <cuda_runtime.h>
#include <cuda_fp16.h>
#include <cstdint>

// MTLSTM: B=128, T=512, K=12, H=256, OUT=1
// Persistent kernel: 128 CTAs x 256 threads.
// fp16 mma.m16n8k16 (B weights in registers), states in padded fp16 global,
// staged per-step via cp.async.bulk + mbarrier, software grid barrier.

#define NB 128
#define NT 512
#define NKF 12
#define NH 256
#define GRID 128
#define THREADS 256
#define PADH 264              // padded state row length (halves); 132 words

__device__ __half g_hs[2][NB * PADH];
__device__ __half g_cs[2][NB * PADH];
__device__ float g_dec[NB * NT * NKF];   // (1/ln(e+dt) - 1)
__device__ unsigned g_bar;

// ---------------- PTX helpers ----------------
__device__ __forceinline__ uint32_t smem_u32(const void* p) {
    return (uint32_t)__cvta_generic_to_shared(p);
}
__device__ __forceinline__ void mbar_init(uint32_t a, uint32_t cnt) {
    asm volatile("mbarrier.init.shared.b64 [%0], %1;" :: "r"(a), "r"(cnt) : "memory");
}
__device__ __forceinline__ void mbar_expect_tx(uint32_t a, uint32_t bytes) {
    asm volatile("mbarrier.arrive.expect_tx.shared.b64 _, [%0], %1;"
                 :: "r"(a), "r"(bytes) : "memory");
}
__device__ __forceinline__ void mbar_wait(uint32_t a, uint32_t parity) {
    asm volatile(
        "{\n\t.reg .pred P;\n\t"
        "W%=: mbarrier.try_wait.parity.acquire.cta.shared::cta.b64 P, [%0], %1, 0x989680;\n\t"
        "@P bra D%=;\n\t"
        "bra W%=;\n\t"
        "D%=:\n\t}"
        :: "r"(a), "r"(parity) : "memory");
}
__device__ __forceinline__ void bulk_g2s(uint32_t dst, const void* src,
                                         uint32_t bytes, uint32_t mbar) {
    asm volatile(
        "cp.async.bulk.shared::cluster.global.mbarrier::complete_tx::bytes "
        "[%0], [%1], %2, [%3];"
        :: "r"(dst), "l"(src), "r"(bytes), "r"(mbar) : "memory");
}
__device__ __forceinline__ void mma_f16(float acc[4],
                                        uint32_t a0, uint32_t a1, uint32_t a2, uint32_t a3,
                                        uint32_t b0, uint32_t b1) {
    asm volatile(
        "mma.sync.aligned.m16n8k16.row.col.f32.f16.f16.f32 "
        "{%0,%1,%2,%3}, {%4,%5,%6,%7}, {%8,%9}, {%0,%1,%2,%3};\n"
        : "+f"(acc[0]), "+f"(acc[1]), "+f"(acc[2]), "+f"(acc[3])
        : "r"(a0), "r"(a1), "r"(a2), "r"(a3), "r"(b0), "r"(b1));
}

__device__ __forceinline__ float sig_f(float x) {
    return __fdividef(1.0f, 1.0f + __expf(-x));
}
__device__ __forceinline__ float tanh_f(float x) {
    x = fminf(15.0f, fmaxf(-15.0f, x));
    float e = __expf(2.0f * x);
    return __fdividef(e - 1.0f, e + 1.0f);
}

// ---- shared memory byte layout ----
//  [0,64)      : 4 mbarriers (h0,h1,c0,c1)
//  [64,+33792) : hA  (64 rows x 264 halves)
//  [..,+33792) : cA
//  Csm float[64*66], sWih[192], sBias[16], sBde[48]
#define SM_MBAR   0
#define SM_HA     64
#define SM_CA     (SM_HA + 33792)
#define SM_CSM    (SM_CA + 33792)
#define SM_WIH    (SM_CSM + 64 * 66 * 4)
#define SM_BIAS   (SM_WIH + 192 * 4)
#define SM_BDE    (SM_BIAS + 16 * 4)
#define SM_TOTAL  (SM_BDE + 48 * 4)

#define HALF_CHUNK 16896u      // 32 rows x 264 halves x 2B

__global__ void __launch_bounds__(THREADS, 1)
mtlstm_persistent(const float* __restrict__ xd, const float* __restrict__ dtp,
                  const float* __restrict__ Wih, const float* __restrict__ Whh,
                  const float* __restrict__ bias, const float* __restrict__ Wd,
                  const float* __restrict__ bde, const float* __restrict__ lw,
                  const float* __restrict__ lb, float* __restrict__ out) {
    extern __shared__ unsigned char smraw[];
    uint32_t* hA32 = reinterpret_cast<uint32_t*>(smraw + SM_HA);
    uint32_t* cA32 = reinterpret_cast<uint32_t*>(smraw + SM_CA);
    float* Csm = reinterpret_cast<float*>(smraw + SM_CSM);
    float* sWih = reinterpret_cast<float*>(smraw + SM_WIH);
    float* sBias = reinterpret_cast<float*>(smraw + SM_BIAS);
    float* sBde = reinterpret_cast<float*>(smraw + SM_BDE);
    const uint32_t smbase = smem_u32(smraw);

    const int tid = threadIdx.x;
    const int mh = blockIdx.x & 1;       // batch half
    const int ns = blockIdx.x >> 1;      // o-slice
    const int o0 = ns * 4;

    if (tid == 0) {
#pragma unroll
        for (int i = 0; i < 4; ++i) mbar_init(smbase + SM_MBAR + 8 * i, 1);
    }

    // ---- small tables ----
    if (tid < 16) {
        int g = tid >> 2, ol = tid & 3;
        sBias[tid] = bias[g * 256 + o0 + ol];
        for (int k = 0; k < NKF; ++k)
            sWih[tid * NKF + k] = Wih[(g * 256 + o0 + ol) * NKF + k];
    }
    if (tid < 48) {
        int kf = tid >> 2, ol = tid & 3;
        sBde[tid] = bde[kf * 256 + o0 + ol];
    }

    // ---- precompute decay-1 into global scratch (once) ----
    {
        const int gt = blockIdx.x * THREADS + tid;
        const int total = NB * NT * NKF;
        for (int i = gt; i < total; i += GRID * THREADS) {
            float v = dtp[i];
            g_dec[i] = 1.0f / __logf(2.71828182845904523536f + v) - 1.0f;
        }
    }

    // ---- warp / lane mapping ----
    const int w = tid >> 5;
    const int lane = tid & 31;
    const int gq = lane >> 2;
    const int tq = lane & 3;
    const int mpos = w >> 2;       // 0..1 : rows [mpos*32, +32)
    const int npos = w & 3;        // 0 -> gate cols (A=h), 1..3 -> decomp (A=c)

    // ---- load B weight fragments into registers as f16x2, once ----
    uint32_t breg[64];             // [nt(2)][ch(16)][2]
#pragma unroll
    for (int nt = 0; nt < 2; ++nt) {
        const int ntile = npos * 2 + nt;
        const int ncol = ntile * 8 + gq;
        const float* row;
        if (ncol < 16) {
            int g = ncol >> 2, ol = ncol & 3;
            row = Whh + (size_t)(g * 256 + o0 + ol) * 256;
        } else {
            int idx = ncol - 16;
            int kf = idx >> 2, ol = idx & 3;
            row = Wd + (size_t)(kf * 256 + o0 + ol) * 256;
        }
#pragma unroll
        for (int ch = 0; ch < 16; ++ch) {
            const int c0 = ch * 16 + 2 * tq;
            __half2 p0 = __floats2half2_rn(row[c0], row[c0 + 1]);
            __half2 p1 = __floats2half2_rn(row[c0 + 8], row[c0 + 9]);
            breg[(nt * 16 + ch) * 2]     = *reinterpret_cast<uint32_t*>(&p0);
            breg[(nt * 16 + ch) * 2 + 1] = *reinterpret_cast<uint32_t*>(&p1);
        }
    }

    // A fragment base (per warp), conflict-free padded layout
    const uint32_t* aw = ((npos == 0) ? hA32 : cA32) + (mpos * 32 + gq) * 132 + tq;
    // which mbarrier this warp waits on: (c? 2:0) + mpos
    const uint32_t my_mbar = smbase + SM_MBAR + 8 * (((npos == 0) ? 0 : 2) + mpos);

    // ---- epilogue mapping ----
    const int eb = tid >> 2;
    const int eol = tid & 3;
    const int gb = mh * 64 + eb;
    const int go = o0 + eol;
    const float* xrow_base = xd + (size_t)gb * NT * NKF;
    const float* dec_base = g_dec + (size_t)gb * NT * NKF;
    float c_reg = 0.0f;

    // ---- pre-barrier: g_dec + tables + mbarrier init visible ----
    __threadfence();
    __syncthreads();
    if (tid == 0) {
        atomicAdd(&g_bar, 1u);
        while (*(volatile unsigned*)&g_bar < (unsigned)GRID) { }
        __threadfence();
    }
    __syncthreads();

    for (int t = 0; t < NT; ++t) {
        const int p = t & 1;       // read buffer p, write 1-p

        // ---- prefetch x, dec for this step (state-independent) ----
        float x[12], d[12];
        {
            const float* xrow = xrow_base + (size_t)t * NKF;
            const float* drow = dec_base + (size_t)t * NKF;
            float4 x0 = __ldg(reinterpret_cast<const float4*>(xrow));
            float4 x1 = __ldg(reinterpret_cast<const float4*>(xrow) + 1);
            float4 x2 = __ldg(reinterpret_cast<const float4*>(xrow) + 2);
            x[0] = x0.x; x[1] = x0.y; x[2] = x0.z; x[3] = x0.w;
            x[4] = x1.x; x[5] = x1.y; x[6] = x1.z; x[7] = x1.w;
            x[8] = x2.x; x[9] = x2.y; x[10] = x2.z; x[11] = x2.w;
            float4 d0 = __ldg(reinterpret_cast<const float4*>(drow));
            float4 d1 = __ldg(reinterpret_cast<const float4*>(drow) + 1);
            float4 d2 = __ldg(reinterpret_cast<const float4*>(drow) + 2);
            d[0] = d0.x; d[1] = d0.y; d[2] = d0.z; d[3] = d0.w;
            d[4] = d1.x; d[5] = d1.y; d[6] = d1.z; d[7] = d1.w;
            d[8] = d2.x; d[9] = d2.y; d[10] = d2.z; d[11] = d2.w;
        }

        float acc[2][2][4];
#pragma unroll
        for (int a = 0; a < 2; ++a)
#pragma unroll
            for (int b = 0; b < 2; ++b)
#pragma unroll
                for (int c = 0; c < 4; ++c) acc[a][b][c] = 0.0f;

        if (t > 0) {
            // tid0: wait grid barrier (all CTAs finished step t-1), then issue TMA
            if (tid == 0) {
                const unsigned target = (unsigned)(t + 1) * GRID;
                while (*(volatile unsigned*)&g_bar < target) { }
                __threadfence();
                const __half* hs = &g_hs[p][(size_t)mh * 64 * PADH];
                const __half* cs = &g_cs[p][(size_t)mh * 64 * PADH];
#pragma unroll
                for (int half = 0; half < 2; ++half) {
                    uint32_t mb = smbase + SM_MBAR + 8 * half;
                    mbar_expect_tx(mb, HALF_CHUNK);
                    bulk_g2s(smbase + SM_HA + half * HALF_CHUNK,
                             hs + half * 32 * PADH, HALF_CHUNK, mb);
                }
#pragma unroll
                for (int half = 0; half < 2; ++half) {
                    uint32_t mb = smbase + SM_MBAR + 8 * (2 + half);
                    mbar_expect_tx(mb, HALF_CHUNK);
                    bulk_g2s(smbase + SM_CA + half * HALF_CHUNK,
                             cs + half * 32 * PADH, HALF_CHUNK, mb);
                }
            }
            // every warp waits only for its own quarter of state
            mbar_wait(my_mbar, (uint32_t)((t - 1) & 1));

#pragma unroll
            for (int ch = 0; ch < 16; ++ch) {
                uint32_t a[2][4];
#pragma unroll
                for (int mt = 0; mt < 2; ++mt) {
                    const uint32_t* ap = aw + mt * 2112 + ch * 8;
                    a[mt][0] = ap[0];
                    a[mt][1] = ap[1056];
                    a[mt][2] = ap[4];
                    a[mt][3] = ap[1060];
                }
#pragma unroll
                for (int mt = 0; mt < 2; ++mt)
#pragma unroll
                    for (int nt = 0; nt < 2; ++nt)
                        mma_f16(acc[mt][nt],
                                a[mt][0], a[mt][1], a[mt][2], a[mt][3],
                                breg[(nt * 16 + ch) * 2],
                                breg[(nt * 16 + ch) * 2 + 1]);
            }
        }

        // ---- dump accumulators to Csm ----
#pragma unroll
        for (int mt = 0; mt < 2; ++mt)
#pragma unroll
            for (int nt = 0; nt < 2; ++nt) {
                const int ntile = npos * 2 + nt;
                const int col0 = ntile * 8 + 2 * tq;
                const int rr = mpos * 32 + mt * 16 + gq;
                *reinterpret_cast<float2*>(&Csm[rr * 66 + col0]) =
                    make_float2(acc[mt][nt][0], acc[mt][nt][1]);
                *reinterpret_cast<float2*>(&Csm[(rr + 8) * 66 + col0]) =
                    make_float2(acc[mt][nt][2], acc[mt][nt][3]);
            }
        __syncthreads();

        // ---- epilogue ----
        {
            float pre[4];
#pragma unroll
            for (int g = 0; g < 4; ++g) {
                float s = Csm[eb * 66 + g * 4 + eol] + sBias[g * 4 + eol];
                const float* wr = &sWih[(g * 4 + eol) * NKF];
#pragma unroll
                for (int k = 0; k < NKF; ++k) s += x[k] * wr[k];
                pre[g] = s;
            }
            float ig = sig_f(pre[0]);
            float fg = sig_f(pre[1]);
            float gg = tanh_f(pre[2]);
            float og = sig_f(pre[3]);

            float S = 0.0f;
#pragma unroll
            for (int k = 0; k < NKF; ++k) {
                float cs = tanh_f(Csm[eb * 66 + 16 + k * 4 + eol] + sBde[k * 4 + eol]);
                S += cs * d[k];
            }

            float cn = fg * (c_reg + S) + ig * gg;
            c_reg = cn;
            float hn = og * tanh_f(cn);
            g_cs[1 - p][gb * PADH + go] = __float2half_rn(cn);
            g_hs[1 - p][gb * PADH + go] = __float2half_rn(hn);
        }

        // ---- arrive grid barrier (no wait here) ----
        __syncthreads();
        __threadfence();
        if (tid == 0) atomicAdd(&g_bar, 1u);
    }

    // ---- final grid barrier, then output ----
    if (tid == 0) {
        const unsigned target = (unsigned)(NT + 1) * GRID;
        while (*(volatile unsigned*)&g_bar < target) { }
        __threadfence();
    }
    __syncthreads();

    if (w == 0) {
        const int b = blockIdx.x;
        const __half* h = &g_hs[0][(size_t)b * PADH];   // step 511 wrote buffer 0
        float s = 0.0f;
        for (int dd = lane; dd < 256; dd += 32)
            s += __half2float(h[dd]) * lw[dd];
#pragma unroll
        for (int off = 16; off; off >>= 1) s += __shfl_xor_sync(0xffffffffu, s, off);
        if (lane == 0) out[b] = s + lb[0];
    }
}

__global__ void mtlstm_barzero() {
    g_bar = 0u;
}

extern "C" void kernel_launch(void* const* d_in, const int* in_sizes, int n_in,
                              void* d_out, int out_size) {
    const float* xd  = (const float*)d_in[0];
    const float* dtp = (const float*)d_in[1];
    const float* wih = (const float*)d_in[2];
    const float* whh = (const float*)d_in[3];
    const float* bia = (const float*)d_in[4];
    const float* wd  = (const float*)d_in[5];
    const float* bde = (const float*)d_in[6];
    const float* lw  = (const float*)d_in[7];
    const float* lb  = (const float*)d_in[8];
    float* out = (float*)d_out;

    cudaFuncSetAttribute(mtlstm_persistent,
                         cudaFuncAttributeMaxDynamicSharedMemorySize, SM_TOTAL);

    mtlstm_barzero<<<1, 1>>>();
    mtlstm_persistent<<<GRID, THREADS, SM_TOTAL>>>(xd, dtp, wih, whh, bia, wd,
                                                   bde, lw, lb, out);
}

// round 8
// speedup vs baseline: 5.7127x; 1.0772x over previous
#include <cuda_runtime.h>
#include <cuda_fp16.h>
#include <cstdint>

// MTLSTM: B=128, T=512, K=12, H=256, OUT=1
// Persistent kernel: 128 CTAs x 256 threads, fp16 mma.m16n8k16.
// State stored in fragment-native permuted fp16 layout so A-fragments are
// single LDS.128; staged via 16x 4KB cp.async.bulk chunks (pipelined over k);
// per-batch-half software grid barriers.

#define NB 128
#define NT 512
#define NKF 12
#define GRID 128
#define THREADS 256

// State layout (halves), strides:
// buf:65536, s(h=0,c=1):32768, mh:16384, mpos:8192, ch:512, mt:256,
// gq:32, tq:8, hi:4, rlo:2, lo:1
__device__ __half g_S[2 * 65536];
__device__ float g_dec[NB * NT * NKF];   // (1/ln(e+dt) - 1)
__device__ unsigned g_barh[2][32];       // per-half step barrier (separate lines)
__device__ unsigned g_bar0;              // init barrier

// ---------------- PTX helpers ----------------
__device__ __forceinline__ uint32_t smem_u32(const void* p) {
    return (uint32_t)__cvta_generic_to_shared(p);
}
__device__ __forceinline__ void mbar_init(uint32_t a, uint32_t cnt) {
    asm volatile("mbarrier.init.shared.b64 [%0], %1;" :: "r"(a), "r"(cnt) : "memory");
}
__device__ __forceinline__ void mbar_expect_tx(uint32_t a, uint32_t bytes) {
    asm volatile("mbarrier.arrive.expect_tx.shared.b64 _, [%0], %1;"
                 :: "r"(a), "r"(bytes) : "memory");
}
__device__ __forceinline__ void mbar_wait(uint32_t a, uint32_t parity) {
    asm volatile(
        "{\n\t.reg .pred P;\n\t"
        "W%=: mbarrier.try_wait.parity.acquire.cta.shared::cta.b64 P, [%0], %1, 0x989680;\n\t"
        "@P bra D%=;\n\t"
        "bra W%=;\n\t"
        "D%=:\n\t}"
        :: "r"(a), "r"(parity) : "memory");
}
__device__ __forceinline__ void bulk_g2s(uint32_t dst, const void* src,
                                         uint32_t bytes, uint32_t mbar) {
    asm volatile(
        "cp.async.bulk.shared::cluster.global.mbarrier::complete_tx::bytes "
        "[%0], [%1], %2, [%3];"
        :: "r"(dst), "l"(src), "r"(bytes), "r"(mbar) : "memory");
}
__device__ __forceinline__ void mma_f16(float acc[4],
                                        uint32_t a0, uint32_t a1, uint32_t a2, uint32_t a3,
                                        uint32_t b0, uint32_t b1) {
    asm volatile(
        "mma.sync.aligned.m16n8k16.row.col.f32.f16.f16.f32 "
        "{%0,%1,%2,%3}, {%4,%5,%6,%7}, {%8,%9}, {%0,%1,%2,%3};\n"
        : "+f"(acc[0]), "+f"(acc[1]), "+f"(acc[2]), "+f"(acc[3])
        : "r"(a0), "r"(a1), "r"(a2), "r"(a3), "r"(b0), "r"(b1));
}

__device__ __forceinline__ float sig_f(float x) {
    return __fdividef(1.0f, 1.0f + __expf(-x));
}
__device__ __forceinline__ float tanh_f(float x) {
    x = fminf(15.0f, fmaxf(-15.0f, x));
    float e = __expf(2.0f * x);
    return __fdividef(e - 1.0f, e + 1.0f);
}
__device__ __forceinline__ float tanha(float x) {
    float r;
    asm("tanh.approx.f32 %0, %1;" : "=f"(r) : "f"(x));
    return r;
}

// ---- smem byte layout ----
#define SM_MBAR   0                      // 16 mbarriers
#define SM_A      128                    // 2 states x 16384 halves = 65536B
#define SM_CSM    (SM_A + 65536)         // 64*66 floats
#define SM_WIH    (SM_CSM + 64 * 66 * 4)
#define SM_BIAS   (SM_WIH + 192 * 4)
#define SM_BDE    (SM_BIAS + 16 * 4)
#define SM_TOTAL  (SM_BDE + 48 * 4)

__global__ void __launch_bounds__(THREADS, 1)
mtlstm_persistent(const float* __restrict__ xd, const float* __restrict__ dtp,
                  const float* __restrict__ Wih, const float* __restrict__ Whh,
                  const float* __restrict__ bias, const float* __restrict__ Wd,
                  const float* __restrict__ bde, const float* __restrict__ lw,
                  const float* __restrict__ lb, float* __restrict__ out) {
    extern __shared__ unsigned char smraw[];
    const __half* sA = reinterpret_cast<const __half*>(smraw + SM_A);
    float* Csm = reinterpret_cast<float*>(smraw + SM_CSM);
    float* sWih = reinterpret_cast<float*>(smraw + SM_WIH);
    float* sBias = reinterpret_cast<float*>(smraw + SM_BIAS);
    float* sBde = reinterpret_cast<float*>(smraw + SM_BDE);
    const uint32_t smbase = smem_u32(smraw);

    const int tid = threadIdx.x;
    const int mh = blockIdx.x & 1;       // batch half
    const int ns = blockIdx.x >> 1;      // o-slice
    const int o0 = ns * 4;

    if (tid == 0) {
#pragma unroll
        for (int i = 0; i < 16; ++i) mbar_init(smbase + SM_MBAR + 8 * i, 1);
    }

    // ---- small tables ----
    if (tid < 16) {
        int g = tid >> 2, ol = tid & 3;
        sBias[tid] = bias[g * 256 + o0 + ol];
        for (int k = 0; k < NKF; ++k)
            sWih[tid * NKF + k] = Wih[(g * 256 + o0 + ol) * NKF + k];
    }
    if (tid < 48) {
        int kf = tid >> 2, ol = tid & 3;
        sBde[tid] = bde[kf * 256 + o0 + ol];
    }

    // ---- precompute decay-1 (once, cooperatively) ----
    {
        const int gt = blockIdx.x * THREADS + tid;
        const int total = NB * NT * NKF;
        for (int i = gt; i < total; i += GRID * THREADS) {
            float v = dtp[i];
            g_dec[i] = 1.0f / __logf(2.71828182845904523536f + v) - 1.0f;
        }
    }

    // ---- warp / lane mapping ----
    const int w = tid >> 5;
    const int lane = tid & 31;
    const int gq = lane >> 2;
    const int tq = lane & 3;
    const int mpos = w >> 2;       // 0..1
    const int npos = w & 3;        // 0 -> gates (A=h), 1..3 -> decomp (A=c)
    const int s_w = (npos == 0) ? 0 : 1;

    // ---- B weight fragments into registers (once) ----
    uint32_t breg[64];             // [nt(2)][ch(16)][2]
#pragma unroll
    for (int nt = 0; nt < 2; ++nt) {
        const int ntile = npos * 2 + nt;
        const int ncol = ntile * 8 + gq;
        const float* row;
        if (ncol < 16) {
            int g = ncol >> 2, ol = ncol & 3;
            row = Whh + (size_t)(g * 256 + o0 + ol) * 256;
        } else {
            int idx = ncol - 16;
            int kf = idx >> 2, ol = idx & 3;
            row = Wd + (size_t)(kf * 256 + o0 + ol) * 256;
        }
#pragma unroll
        for (int ch = 0; ch < 16; ++ch) {
            const int c0 = ch * 16 + 2 * tq;
            __half2 p0 = __floats2half2_rn(row[c0], row[c0 + 1]);
            __half2 p1 = __floats2half2_rn(row[c0 + 8], row[c0 + 9]);
            breg[(nt * 16 + ch) * 2]     = *reinterpret_cast<uint32_t*>(&p0);
            breg[(nt * 16 + ch) * 2 + 1] = *reinterpret_cast<uint32_t*>(&p1);
        }
    }

    // per-warp A base in smem (halves): s*16384 + mpos*8192, lane part gq*32+tq*8
    const __half* awarp = sA + s_w * 16384 + mpos * 8192 + gq * 32 + tq * 8;
    const uint32_t my_mbar0 = smbase + SM_MBAR + 8 * ((s_w * 2 + mpos) * 4);

    // ---- epilogue mapping ----
    const int eb = tid >> 2;
    const int eol = tid & 3;
    const int gb = mh * 64 + eb;
    const int go = o0 + eol;
    // writer offset into state layout (excluding buf & s strides)
    const int woff = mh * 16384 + (eb >> 5) * 8192 + (go >> 4) * 512 +
                     (((eb >> 3) & 3) >> 1) * 256 + (eb & 7) * 32 +
                     (((go & 15) >> 1) & 3) * 8 + ((go & 15) >> 3) * 4 +
                     (((eb >> 3) & 1)) * 2 + (go & 1);
    const float* xrow_base = xd + (size_t)gb * NT * NKF;
    const float* dec_base = g_dec + (size_t)gb * NT * NKF;
    float c_reg = 0.0f;

    volatile unsigned* barh = &g_barh[mh][0];

    // ---- init barrier: g_dec, tables, mbarriers visible ----
    __threadfence();
    __syncthreads();
    if (tid == 0) {
        atomicAdd(&g_bar0, 1u);
        while (*(volatile unsigned*)&g_bar0 < (unsigned)GRID) { }
        __threadfence();
    }
    __syncthreads();

    for (int t = 0; t < NT; ++t) {
        const int p = t & 1;       // read buffer p, write 1-p

        // ---- prefetch x, dec ----
        float x[12], d[12];
        {
            const float* xrow = xrow_base + (size_t)t * NKF;
            const float* drow = dec_base + (size_t)t * NKF;
            float4 x0 = reinterpret_cast<const float4*>(xrow)[0];
            float4 x1 = reinterpret_cast<const float4*>(xrow)[1];
            float4 x2 = reinterpret_cast<const float4*>(xrow)[2];
            x[0] = x0.x; x[1] = x0.y; x[2] = x0.z; x[3] = x0.w;
            x[4] = x1.x; x[5] = x1.y; x[6] = x1.z; x[7] = x1.w;
            x[8] = x2.x; x[9] = x2.y; x[10] = x2.z; x[11] = x2.w;
            float4 d0 = reinterpret_cast<const float4*>(drow)[0];
            float4 d1 = reinterpret_cast<const float4*>(drow)[1];
            float4 d2 = reinterpret_cast<const float4*>(drow)[2];
            d[0] = d0.x; d[1] = d0.y; d[2] = d0.z; d[3] = d0.w;
            d[4] = d1.x; d[5] = d1.y; d[6] = d1.z; d[7] = d1.w;
            d[8] = d2.x; d[9] = d2.y; d[10] = d2.z; d[11] = d2.w;
        }

        float acc[2][2][4];
#pragma unroll
        for (int a = 0; a < 2; ++a)
#pragma unroll
            for (int b = 0; b < 2; ++b)
#pragma unroll
                for (int c = 0; c < 4; ++c) acc[a][b][c] = 0.0f;

        if (t > 0) {
            if (tid == 0) {
                const unsigned target = (unsigned)t * (GRID / 2);
                while (*barh < target) { }
                __threadfence();
                const __half* gsrc = g_S + (size_t)p * 65536 + mh * 16384;
#pragma unroll
                for (int chq = 0; chq < 4; ++chq) {
#pragma unroll
                    for (int s = 1; s >= 0; --s) {       // c first (6 of 8 warps)
#pragma unroll
                        for (int mp = 0; mp < 2; ++mp) {
                            uint32_t mb = smbase + SM_MBAR + 8 * ((s * 2 + mp) * 4 + chq);
                            mbar_expect_tx(mb, 4096);
                            bulk_g2s(smbase + SM_A + (s * 16384 + mp * 8192 + chq * 2048) * 2,
                                     gsrc + s * 32768 + mp * 8192 + chq * 2048, 4096, mb);
                        }
                    }
                }
            }
            const uint32_t par = (uint32_t)((t - 1) & 1);
#pragma unroll
            for (int chq = 0; chq < 4; ++chq) {
                mbar_wait(my_mbar0 + 8 * chq, par);
#pragma unroll
                for (int c4 = 0; c4 < 4; ++c4) {
                    const int ch = chq * 4 + c4;
                    uint4 va = *reinterpret_cast<const uint4*>(awarp + ch * 512);
                    uint4 vb = *reinterpret_cast<const uint4*>(awarp + ch * 512 + 256);
#pragma unroll
                    for (int nt = 0; nt < 2; ++nt) {
                        mma_f16(acc[0][nt], va.x, va.y, va.z, va.w,
                                breg[(nt * 16 + ch) * 2], breg[(nt * 16 + ch) * 2 + 1]);
                        mma_f16(acc[1][nt], vb.x, vb.y, vb.z, vb.w,
                                breg[(nt * 16 + ch) * 2], breg[(nt * 16 + ch) * 2 + 1]);
                    }
                }
            }
        }

        // ---- dump accumulators to Csm ----
#pragma unroll
        for (int mt = 0; mt < 2; ++mt)
#pragma unroll
            for (int nt = 0; nt < 2; ++nt) {
                const int ntile = npos * 2 + nt;
                const int col0 = ntile * 8 + 2 * tq;
                const int rr = mpos * 32 + mt * 16 + gq;
                *reinterpret_cast<float2*>(&Csm[rr * 66 + col0]) =
                    make_float2(acc[mt][nt][0], acc[mt][nt][1]);
                *reinterpret_cast<float2*>(&Csm[(rr + 8) * 66 + col0]) =
                    make_float2(acc[mt][nt][2], acc[mt][nt][3]);
            }
        __syncthreads();

        // ---- epilogue ----
        {
            float pre[4];
#pragma unroll
            for (int g = 0; g < 4; ++g) {
                float s = Csm[eb * 66 + g * 4 + eol] + sBias[g * 4 + eol];
                const float* wr = &sWih[(g * 4 + eol) * NKF];
#pragma unroll
                for (int k = 0; k < NKF; ++k) s += x[k] * wr[k];
                pre[g] = s;
            }
            float ig = sig_f(pre[0]);
            float fg = sig_f(pre[1]);
            float gg = tanha(pre[2]);
            float og = sig_f(pre[3]);

            float S = 0.0f;
#pragma unroll
            for (int k = 0; k < NKF; ++k) {
                float cs = tanha(Csm[eb * 66 + 16 + k * 4 + eol] + sBde[k * 4 + eol]);
                S += cs * d[k];
            }

            float cn = fg * (c_reg + S) + ig * gg;
            c_reg = cn;
            float hn = og * tanh_f(cn);
            __half* gdst = g_S + (size_t)(1 - p) * 65536 + woff;
            gdst[0] = __float2half_rn(hn);          // s=0 (h)
            gdst[32768] = __float2half_rn(cn);      // s=1 (c)
        }

        // ---- arrive per-half barrier ----
        __syncthreads();
        __threadfence();
        if (tid == 0) atomicAdd((unsigned*)barh, 1u);
    }

    // ---- final barrier, then output ----
    if (tid == 0) {
        const unsigned target = (unsigned)NT * (GRID / 2);
        while (*barh < target) { }
        __threadfence();
    }
    __syncthreads();

    if (w == 0) {
        const int b = blockIdx.x;
        const int bmh = b >> 6;
        const int r = b & 63;
        const int rpart = bmh * 16384 + (r >> 5) * 8192 + (((r >> 3) & 3) >> 1) * 256 +
                          (r & 7) * 32 + ((r >> 3) & 1) * 2;
        float ssum = 0.0f;
        for (int dd = lane; dd < 256; dd += 32) {
            const int kk = dd & 15;
            const int off = rpart + (dd >> 4) * 512 + ((kk >> 1) & 3) * 8 +
                            (kk >> 3) * 4 + (kk & 1);
            ssum += __half2float(g_S[off]) * lw[dd];   // buf 0, s=0 (h)
        }
#pragma unroll
        for (int off = 16; off; off >>= 1) ssum += __shfl_xor_sync(0xffffffffu, ssum, off);
        if (lane == 0) out[b] = ssum + lb[0];
    }
}

__global__ void mtlstm_barzero() {
    g_bar0 = 0u;
    g_barh[0][0] = 0u;
    g_barh[1][0] = 0u;
}

extern "C" void kernel_launch(void* const* d_in, const int* in_sizes, int n_in,
                              void* d_out, int out_size) {
    const float* xd  = (const float*)d_in[0];
    const float* dtp = (const float*)d_in[1];
    const float* wih = (const float*)d_in[2];
    const float* whh = (const float*)d_in[3];
    const float* bia = (const float*)d_in[4];
    const float* wd  = (const float*)d_in[5];
    const float* bde = (const float*)d_in[6];
    const float* lw  = (const float*)d_in[7];
    const float* lb  = (const float*)d_in[8];
    float* out = (float*)d_out;

    cudaFuncSetAttribute(mtlstm_persistent,
                         cudaFuncAttributeMaxDynamicSharedMemorySize, SM_TOTAL);

    mtlstm_barzero<<<1, 1>>>();
    mtlstm_persistent<<<GRID, THREADS, SM_TOTAL>>>(xd, dtp, wih, whh, bia, wd,
                                                   bde, lw, lb, out);
}